// round 4
// baseline (speedup 1.0000x reference)
#include <cuda_runtime.h>
#include <cuda_bf16.h>
#include <cstdint>

// Problem constants (fixed by the reference)
#define B_    4
#define C_    512
#define H_    64
#define W_    208
#define HID_  512
#define DS_   16
#define NREG_ 4

#define DT_   16   // d-tiles of 32 (one 128B sector)
#define SG_   16   // reduction subgroups per block (512 threads)

// Fused-kernel block roles
#define NBLK1_ 64            // stage1 blocks  (blockIdx 0..63)
#define NBLKP_ B_            // perm blocks    (blockIdx 64..67)
#define NBLK2_ 64            // stage2 blocks  (blockIdx 68..131)
#define NBLKF_ (NBLK1_ + NBLKP_ + NBLK2_)   // 132 <= 148 SMs -> all co-resident

// Scratch (device globals; no allocation allowed)
__device__ float g_tmp  [NREG_ * B_ * HID_];  // tmp[r, b, d]
__device__ float g_delta[B_ * NREG_ * C_];    // delta[b, r, c]
__device__ int   g_perm[B_ * W_];             // output col w -> source col
__device__ int   g_reg [B_ * W_];             // output col w -> region id (0..3)
__device__ int   g_done = 0;                  // stage1 arrival counter

// ---------------------------------------------------------------------------
// Fused setup kernel. 132 blocks x 512 threads, all resident in wave 1:
//   blocks [0,64):    tmp[r,b,d] = sum_h tf[r,b,h] * Wv[r,h,d]
//   blocks [64,68):   stable counting-sort perm per batch (parallel rank)
//   blocks [68,132):  delta[b,r,c] = sum_d tmp[r,b,d] * Wo[r,d,c]
//                     (spin-waits on g_done until all 64 stage1 blocks done)
// g_done is reset by the gather kernel (stream order => visible next replay).
// ---------------------------------------------------------------------------
__global__ __launch_bounds__(512) void setup_fused(
        const float* __restrict__ text_feat,
        const float* __restrict__ Wv,
        const float* __restrict__ Wo,
        const int*   __restrict__ text_mask) {
    const int blk = blockIdx.x;
    const int tid = threadIdx.x;

    if (blk < NBLK1_) {
        // ---------------- stage 1 ----------------
        const int r  = blk / DT_;
        const int dt = blk % DT_;
        const int dl = tid & 31;
        const int hs = tid >> 5;          // 0..15
        const int d  = dt * 32 + dl;

        __shared__ float s_tf[B_][HID_];
        for (int i = tid; i < B_ * HID_; i += 512)
            s_tf[i / HID_][i % HID_] = text_feat[(size_t)r * B_ * HID_ + i];
        __syncthreads();

        const float* wv = Wv + (size_t)r * HID_ * HID_ + d;
        float acc[B_] = {0.f, 0.f, 0.f, 0.f};
        #pragma unroll 16
        for (int h = hs; h < HID_; h += SG_) {
            const float w = wv[(size_t)h * HID_];
            #pragma unroll
            for (int b = 0; b < B_; ++b)
                acc[b] = fmaf(s_tf[b][h], w, acc[b]);
        }

        __shared__ float s_red[SG_][B_][32];
        #pragma unroll
        for (int b = 0; b < B_; ++b) s_red[hs][b][dl] = acc[b];
        __syncthreads();

        if (hs == 0) {
            #pragma unroll
            for (int b = 0; b < B_; ++b) {
                float s = 0.f;
                #pragma unroll
                for (int g = 0; g < SG_; ++g) s += s_red[g][b][dl];
                g_tmp[((size_t)r * B_ + b) * HID_ + d] = s;
            }
        }
        __syncthreads();
        __threadfence();
        if (tid == 0) atomicAdd(&g_done, 1);

    } else if (blk < NBLK1_ + NBLKP_) {
        // ---------------- perm (stable counting sort, parallel rank) -------
        const int b = blk - NBLK1_;
        __shared__ int s_lab[W_];
        const size_t mask_batch_stride = (size_t)(H_ * DS_) * (W_ * DS_);

        if (tid < W_)
            s_lab[tid] = text_mask[b * mask_batch_stride + (size_t)tid * DS_];
        __syncthreads();

        if (tid < W_) {
            const int lab = s_lab[tid];
            int pos = 0;
            #pragma unroll 8
            for (int w2 = 0; w2 < W_; ++w2) {
                const int l2 = s_lab[w2];
                pos += (l2 < lab) || (l2 == lab && w2 < tid);
            }
            g_perm[b * W_ + pos] = tid;
            g_reg [b * W_ + pos] = lab - 1;
        }

    } else {
        // ---------------- stage 2 ----------------
        const int id = blk - NBLK1_ - NBLKP_;
        const int r  = id / DT_;
        const int ct = id % DT_;
        const int cl = tid & 31;
        const int ds = tid >> 5;
        const int c  = ct * 32 + cl;

        if (tid == 0) {
            while (*((volatile int*)&g_done) < NBLK1_) { }
        }
        __syncthreads();
        __threadfence();

        __shared__ float s_tmp[B_][HID_];
        for (int i = tid; i < B_ * HID_; i += 512)
            s_tmp[i / HID_][i % HID_] = __ldcg(&g_tmp[(size_t)r * B_ * HID_ + i]);
        __syncthreads();

        const float* wo = Wo + (size_t)r * HID_ * C_ + c;
        float acc[B_] = {0.f, 0.f, 0.f, 0.f};
        #pragma unroll 16
        for (int d = ds; d < HID_; d += SG_) {
            const float w = wo[(size_t)d * C_];
            #pragma unroll
            for (int b = 0; b < B_; ++b)
                acc[b] = fmaf(s_tmp[b][d], w, acc[b]);
        }

        __shared__ float s_red[SG_][B_][32];
        #pragma unroll
        for (int b = 0; b < B_; ++b) s_red[ds][b][cl] = acc[b];
        __syncthreads();

        if (ds == 0) {
            #pragma unroll
            for (int b = 0; b < B_; ++b) {
                float s = 0.f;
                #pragma unroll
                for (int g = 0; g < SG_; ++g) s += s_red[g][b][cl];
                g_delta[((size_t)b * NREG_ + r) * C_ + c] = s;
            }
        }
    }
}

// ---------------------------------------------------------------------------
// Gather v2: out[b,c,h,w] = image[b,c,h, perm[b,w]] + delta[b, reg[b,w], c]
// Each block stages TILE_R=16 rows into smem with coalesced float4 loads,
// then permutes out of smem (scatter moves from L1tex to LDS crossbar).
// b and c are uniform per tile (16 | 64 = H_, 16 | 32768 = C_*H_).
// ---------------------------------------------------------------------------
#define TILE_R_  16
#define ROW4_    (W_ / 4)                       // 52
#define TILE4_   (TILE_R_ * ROW4_)              // 832 float4 per block
#define SROW_    212                            // padded smem row stride (floats)
#define NROWS_   (B_ * C_ * H_)                 // 131072
#define NGBLK_   (NROWS_ / TILE_R_)             // 8192

__global__ __launch_bounds__(256) void gather_add_kernel(
        const float* __restrict__ image, float* __restrict__ out) {
    __shared__ float s_img[TILE_R_][SROW_];
    __shared__ __align__(16) int s_perm[W_];
    __shared__ __align__(16) int s_reg[W_];
    __shared__ float s_delta[NREG_];

    const int tid  = threadIdx.x;
    const int row0 = blockIdx.x * TILE_R_;
    const int b    = row0 / (C_ * H_);          // uniform per tile
    const int c    = (row0 / H_) % C_;          // uniform per tile

    // reset the setup kernel's arrival counter for the next graph replay
    if (blockIdx.x == 0 && tid == 0) g_done = 0;

    // stage LUTs
    if (tid < W_) {
        s_perm[tid] = g_perm[b * W_ + tid];
        s_reg [tid] = g_reg [b * W_ + tid];
    }
    if (tid < NREG_)
        s_delta[tid] = g_delta[((size_t)b * NREG_ + tid) * C_ + c];

    // stage image rows: coalesced float4 loads
    const float* imbase = image + (size_t)row0 * W_;
    for (int i = tid; i < TILE4_; i += 256) {
        const int rl = i / ROW4_;
        const int w4 = i % ROW4_;
        const float4 v = reinterpret_cast<const float4*>(imbase)[(size_t)rl * ROW4_ + w4];
        s_img[rl][w4 * 4 + 0] = v.x;
        s_img[rl][w4 * 4 + 1] = v.y;
        s_img[rl][w4 * 4 + 2] = v.z;
        s_img[rl][w4 * 4 + 3] = v.w;
    }
    __syncthreads();

    // permute out of smem, coalesced float4 stores
    float4* obase = reinterpret_cast<float4*>(out) + (size_t)row0 * ROW4_;
    for (int i = tid; i < TILE4_; i += 256) {
        const int rl = i / ROW4_;
        const int w  = (i % ROW4_) * 4;

        const int4 s4 = *reinterpret_cast<const int4*>(&s_perm[w]);
        const int4 r4 = *reinterpret_cast<const int4*>(&s_reg [w]);

        float4 o;
        o.x = s_img[rl][s4.x] + s_delta[r4.x];
        o.y = s_img[rl][s4.y] + s_delta[r4.y];
        o.z = s_img[rl][s4.z] + s_delta[r4.z];
        o.w = s_img[rl][s4.w] + s_delta[r4.w];
        obase[i] = o;
    }
}

// ---------------------------------------------------------------------------
// Launch. Input order (metadata): image_feature f32, text_feat f32,
// text_mask i32, Wq f32 (unused), Wk f32 (unused), Wv f32, Wo f32.
// ---------------------------------------------------------------------------
extern "C" void kernel_launch(void* const* d_in, const int* in_sizes, int n_in,
                              void* d_out, int out_size) {
    const float* image     = (const float*)d_in[0];
    const float* text_feat = (const float*)d_in[1];
    const int*   text_mask = (const int*)  d_in[2];
    const float* Wv        = (const float*)d_in[5];
    const float* Wo        = (const float*)d_in[6];
    float* out = (float*)d_out;

    setup_fused<<<NBLKF_, 512>>>(text_feat, Wv, Wo, text_mask);
    gather_add_kernel<<<NGBLK_, 256>>>(image, out);
}